// round 16
// baseline (speedup 1.0000x reference)
#include <cuda_runtime.h>

#define D 128
#define NEG 0.01f
#define MAXU 100000
#define MAXI 50000

// Scratch (sanctioned __device__ globals). float4-typed => 16B alignment.
__device__ float4 g_uf4[MAXU * (D / 4)];
__device__ float4 g_if4[MAXI * (D / 4)];
// Flags written by prepass each launch: [0]=A is int64, [1]=B is int64,
// [2]=swap (A holds dst, B holds src)
__device__ int g_flags[3];

__device__ __forceinline__ float lrelu(float x) { return x >= 0.f ? x : NEG * x; }

// ---------------------------------------------------------------------------
// Prepass: detect per-array index dtype (int64 => odd 32-bit words all zero)
// and decide which array is src (its sampled max >= NI; dst < NI always).
// ---------------------------------------------------------------------------
__global__ void prepass_kernel(const unsigned* __restrict__ A,
                               const unsigned* __restrict__ B,
                               int E, int forceA64, int forceB64, int NI)
{
    __shared__ int nz[2];
    __shared__ int mx[2];
    int tid = threadIdx.x;
    if (tid < 2) { nz[tid] = 0; mx[tid] = 0; }
    __syncthreads();

    int n = E < 1024 ? E : 1024;
    unsigned a = 0, b = 0;
    for (int i = tid; i < n; i += blockDim.x) {
        a |= A[2 * i + 1];
        b |= B[2 * i + 1];
    }
    if (a) atomicOr(&nz[0], 1);
    if (b) atomicOr(&nz[1], 1);
    __syncthreads();

    int a64 = forceA64 | (nz[0] ? 0 : 1);
    int b64 = forceB64 | (nz[1] ? 0 : 1);

    int ma = 0, mb = 0;
    for (int i = tid; i < E; i += blockDim.x * 8) {
        int va = a64 ? (int)((const long long*)A)[i] : ((const int*)A)[i];
        int vb = b64 ? (int)((const long long*)B)[i] : ((const int*)B)[i];
        ma = va > ma ? va : ma;
        mb = vb > mb ? vb : mb;
    }
    atomicMax(&mx[0], ma);
    atomicMax(&mx[1], mb);
    __syncthreads();

    if (tid == 0) {
        g_flags[0] = a64;
        g_flags[1] = b64;
        g_flags[2] = (mx[0] < NI && mx[1] >= NI) ? 1 : 0;
    }
}

__device__ __forceinline__ int load_idx(const void* p, int i, int is64, int lim)
{
    int v = is64 ? (int)((const long long*)p)[i] : ((const int*)p)[i];
    v = v < 0 ? 0 : v;
    v = v >= lim ? lim - 1 : v;
    return v;
}

// Shared memory layout (floats):
//   [0,16384) W   [16384,16512) b1   [16512,16640) w2   [16640,16644) b2
//   [16644, +8*4*128) xs (8 warps * 4 rows * 128)
constexpr int SM_W  = 0;
constexpr int SM_B1 = 16384;
constexpr int SM_W2 = 16512;
constexpr int SM_B2 = 16640;
constexpr int SM_XS = 16644;
constexpr int SMEM_FLOATS = SM_XS + 8 * 4 * D;   // 20740 floats = 82960 B

// Micro-tile GEMM: 4 rows (staged in xs) x D=128 cols.
// Each lane owns 4 columns: j = lane + 32*jj, jj in [0,4).
__device__ __forceinline__ void tile_gemm(const float* __restrict__ xs,
                                          const float* __restrict__ Ws,
                                          int lane, float acc[4][4])
{
    #pragma unroll
    for (int e = 0; e < 4; e++)
        #pragma unroll
        for (int jj = 0; jj < 4; jj++) acc[e][jj] = 0.f;

    #pragma unroll 1
    for (int k = 0; k < D; k += 4) {
        float4 xv0 = *(const float4*)(xs + 0 * D + k);
        float4 xv1 = *(const float4*)(xs + 1 * D + k);
        float4 xv2 = *(const float4*)(xs + 2 * D + k);
        float4 xv3 = *(const float4*)(xs + 3 * D + k);
        {
            const float* wrow = Ws + (k + 0) * D + lane;
            #pragma unroll
            for (int jj = 0; jj < 4; jj++) {
                float w = wrow[32 * jj];
                acc[0][jj] += xv0.x * w; acc[1][jj] += xv1.x * w;
                acc[2][jj] += xv2.x * w; acc[3][jj] += xv3.x * w;
            }
        }
        {
            const float* wrow = Ws + (k + 1) * D + lane;
            #pragma unroll
            for (int jj = 0; jj < 4; jj++) {
                float w = wrow[32 * jj];
                acc[0][jj] += xv0.y * w; acc[1][jj] += xv1.y * w;
                acc[2][jj] += xv2.y * w; acc[3][jj] += xv3.y * w;
            }
        }
        {
            const float* wrow = Ws + (k + 2) * D + lane;
            #pragma unroll
            for (int jj = 0; jj < 4; jj++) {
                float w = wrow[32 * jj];
                acc[0][jj] += xv0.z * w; acc[1][jj] += xv1.z * w;
                acc[2][jj] += xv2.z * w; acc[3][jj] += xv3.z * w;
            }
        }
        {
            const float* wrow = Ws + (k + 3) * D + lane;
            #pragma unroll
            for (int jj = 0; jj < 4; jj++) {
                float w = wrow[32 * jj];
                acc[0][jj] += xv0.w * w; acc[1][jj] += xv1.w * w;
                acc[2][jj] += xv2.w * w; acc[3][jj] += xv3.w * w;
            }
        }
    }
}

// ---------------------------------------------------------------------------
// Node linear: out[r] = X[r] @ W + b
// ---------------------------------------------------------------------------
__global__ void node_linear_kernel(const float* __restrict__ X,
                                   const float* __restrict__ W,
                                   const float* __restrict__ b,
                                   float* __restrict__ out, int N)
{
    extern __shared__ float sm[];
    float* Ws = sm + SM_W;
    float* bs = sm + SM_B1;
    float* xsAll = sm + SM_XS;

    int tid = threadIdx.x;
    {
        const float4* s4 = (const float4*)W;
        float4* d4 = (float4*)Ws;
        for (int i = tid; i < (D * D) / 4; i += blockDim.x) d4[i] = s4[i];
        for (int i = tid; i < D; i += blockDim.x) bs[i] = b[i];
    }
    __syncthreads();

    int wid = tid >> 5, lane = tid & 31;
    float* xs = xsAll + wid * (4 * D);

    int groups = (N + 31) >> 5;
    for (int g = blockIdx.x; g < groups; g += gridDim.x) {
        int rbase = g * 32 + wid * 4;
        __syncwarp();
        #pragma unroll
        for (int e = 0; e < 4; e++) {
            int r = rbase + e;
            if (r < N) {
                float4 v = ((const float4*)(X + (size_t)r * D))[lane];
                ((float4*)(xs + e * D))[lane] = v;
            }
        }
        __syncwarp();

        float acc[4][4];
        tile_gemm(xs, Ws, lane, acc);

        #pragma unroll
        for (int e = 0; e < 4; e++) {
            int r = rbase + e;
            if (r < N) {
                #pragma unroll
                for (int jj = 0; jj < 4; jj++) {
                    int j = lane + 32 * jj;
                    out[(size_t)r * D + j] = acc[e][jj] + bs[j];
                }
            }
        }
    }
}

// ---------------------------------------------------------------------------
// Edge kernel: gather + add + LReLU -> @W1+b1 -> LReLU -> @W2+b2 -> LReLU
// ---------------------------------------------------------------------------
__global__ void edge_mlp_kernel(const float* __restrict__ uf,
                                const float* __restrict__ itf,
                                const void* __restrict__ idxA,
                                const void* __restrict__ idxB,
                                const float* __restrict__ W1,
                                const float* __restrict__ b1,
                                const float* __restrict__ W2,
                                const float* __restrict__ b2,
                                float* __restrict__ out,
                                int E, int NU, int NI)
{
    extern __shared__ float sm[];
    float* Ws  = sm + SM_W;
    float* b1s = sm + SM_B1;
    float* w2s = sm + SM_W2;
    float* b2s = sm + SM_B2;
    float* xsAll = sm + SM_XS;

    int tid = threadIdx.x;
    {
        const float4* s4 = (const float4*)W1;
        float4* d4 = (float4*)Ws;
        for (int i = tid; i < (D * D) / 4; i += blockDim.x) d4[i] = s4[i];
        for (int i = tid; i < D; i += blockDim.x) { b1s[i] = b1[i]; w2s[i] = W2[i]; }
        if (tid == 0) b2s[0] = b2[0];
    }
    __syncthreads();

    int a64 = g_flags[0], b64 = g_flags[1], swp = g_flags[2];
    const void* src = swp ? idxB : idxA;
    const void* dst = swp ? idxA : idxB;
    int s64 = swp ? b64 : a64;
    int d64 = swp ? a64 : b64;

    int wid = tid >> 5, lane = tid & 31;
    float* xs = xsAll + wid * (4 * D);

    int groups = (E + 31) >> 5;
    for (int g = blockIdx.x; g < groups; g += gridDim.x) {
        int ebase = g * 32 + wid * 4;
        __syncwarp();
        #pragma unroll
        for (int e = 0; e < 4; e++) {
            int eid = ebase + e;
            if (eid < E) {
                int s = load_idx(src, eid, s64, NU);
                int d = load_idx(dst, eid, d64, NI);
                float4 a = ((const float4*)(uf  + (size_t)s * D))[lane];
                float4 c = ((const float4*)(itf + (size_t)d * D))[lane];
                float4 v;
                v.x = lrelu(a.x + c.x);
                v.y = lrelu(a.y + c.y);
                v.z = lrelu(a.z + c.z);
                v.w = lrelu(a.w + c.w);
                ((float4*)(xs + e * D))[lane] = v;
            }
        }
        __syncwarp();

        float acc[4][4];
        tile_gemm(xs, Ws, lane, acc);

        float b2v = b2s[0];
        #pragma unroll
        for (int e = 0; e < 4; e++) {
            float p = 0.f;
            #pragma unroll
            for (int jj = 0; jj < 4; jj++) {
                int j = lane + 32 * jj;
                float y = lrelu(acc[e][jj] + b1s[j]);
                p += y * w2s[j];
            }
            #pragma unroll
            for (int off = 16; off; off >>= 1)
                p += __shfl_xor_sync(0xffffffffu, p, off);
            int eid = ebase + e;
            if (lane == 0 && eid < E)
                out[eid] = lrelu(p + b2v);
        }
    }
}

extern "C" void kernel_launch(void* const* d_in, const int* in_sizes, int n_in,
                              void* d_out, int out_size)
{
    float* out = (float*)d_out;
    int E = out_size;                 // ground truth edge count

    // ---- DICT-ORDER binding (metadata.txt = setup_inputs() dict order) ----
    //   0 h_user, 1 h_item, 2 src_idx, 3 dst_idx,
    //   4 W_left, 5 b_left, 6 W_right, 7 b_right,
    //   8 W1, 9 b1, 10 W2, 11 b2
    const float* h_user  = (const float*)d_in[0];
    const float* h_item  = (const float*)d_in[1];
    const void*  idxA    = d_in[2];
    const void*  idxB    = d_in[3];
    const float* W_left  = (const float*)d_in[4];
    const float* b_left  = (const float*)d_in[5];
    const float* W_right = (const float*)d_in[6];
    const float* b_right = (const float*)d_in[7];
    const float* W1      = (const float*)d_in[8];
    const float* b1      = (const float*)d_in[9];
    const float* W2      = (const float*)d_in[10];
    const float* b2      = (const float*)d_in[11];

    long long szU = in_sizes[0], szI = in_sizes[1];
    // larger feature matrix is h_user (robustness; dict order already has it)
    if (szI > szU) {
        const float* t = h_user; h_user = h_item; h_item = t;
        long long ts = szU; szU = szI; szI = ts;
    }
    int NU = (int)(szU / D); if (NU > MAXU) NU = MAXU;
    int NI = (int)(szI / D); if (NI > MAXI) NI = MAXI;
    int forceA64 = (in_sizes[2] == 2 * E) ? 1 : 0;
    int forceB64 = (in_sizes[3] == 2 * E) ? 1 : 0;

    float *uf, *itf;
    cudaGetSymbolAddress((void**)&uf,  g_uf4);
    cudaGetSymbolAddress((void**)&itf, g_if4);

    size_t smem = SMEM_FLOATS * sizeof(float);
    cudaFuncSetAttribute(node_linear_kernel,
                         cudaFuncAttributeMaxDynamicSharedMemorySize, (int)smem);
    cudaFuncSetAttribute(edge_mlp_kernel,
                         cudaFuncAttributeMaxDynamicSharedMemorySize, (int)smem);

    prepass_kernel<<<1, 1024>>>((const unsigned*)idxA, (const unsigned*)idxB,
                                E, forceA64, forceB64, NI);
    node_linear_kernel<<<(NU + 31) / 32, 256, smem>>>(h_user, W_left, b_left, uf, NU);
    node_linear_kernel<<<(NI + 31) / 32, 256, smem>>>(h_item, W_right, b_right, itf, NI);
    edge_mlp_kernel<<<296, 256, smem>>>(uf, itf, idxA, idxB, W1, b1, W2, b2, out,
                                        E, NU, NI);
}

// round 17
// speedup vs baseline: 1.2584x; 1.2584x over previous
#include <cuda_runtime.h>

#define D 128
#define NEG 0.01f
#define MAXU 100000
#define MAXI 50000

typedef unsigned long long ull;

__device__ float4 g_uf4[MAXU * (D / 4)];
__device__ float4 g_if4[MAXI * (D / 4)];
__device__ int g_flags[3];

__device__ __forceinline__ float lrelu(float x) { return x >= 0.f ? x : NEG * x; }

__device__ __forceinline__ ull pack2(float x, float y) {
    ull r; asm("mov.b64 %0, {%1, %2};" : "=l"(r) : "f"(x), "f"(y)); return r;
}
__device__ __forceinline__ void unpack2(ull v, float& x, float& y) {
    asm("mov.b64 {%0, %1}, %2;" : "=f"(x), "=f"(y) : "l"(v));
}
__device__ __forceinline__ ull fma2(ull a, ull b, ull c) {
    ull d; asm("fma.rn.f32x2 %0, %1, %2, %3;" : "=l"(d) : "l"(a), "l"(b), "l"(c));
    return d;
}

// ---------------------------------------------------------------------------
__global__ void prepass_kernel(const unsigned* __restrict__ A,
                               const unsigned* __restrict__ B,
                               int E, int forceA64, int forceB64, int NI)
{
    __shared__ int nz[2];
    __shared__ int mx[2];
    int tid = threadIdx.x;
    if (tid < 2) { nz[tid] = 0; mx[tid] = 0; }
    __syncthreads();

    int n = E < 1024 ? E : 1024;
    unsigned a = 0, b = 0;
    for (int i = tid; i < n; i += blockDim.x) { a |= A[2 * i + 1]; b |= B[2 * i + 1]; }
    if (a) atomicOr(&nz[0], 1);
    if (b) atomicOr(&nz[1], 1);
    __syncthreads();

    int a64 = forceA64 | (nz[0] ? 0 : 1);
    int b64 = forceB64 | (nz[1] ? 0 : 1);

    int ma = 0, mb = 0;
    for (int i = tid; i < E; i += blockDim.x * 8) {
        int va = a64 ? (int)((const long long*)A)[i] : ((const int*)A)[i];
        int vb = b64 ? (int)((const long long*)B)[i] : ((const int*)B)[i];
        ma = va > ma ? va : ma;
        mb = vb > mb ? vb : mb;
    }
    atomicMax(&mx[0], ma);
    atomicMax(&mx[1], mb);
    __syncthreads();

    if (tid == 0) {
        g_flags[0] = a64;
        g_flags[1] = b64;
        g_flags[2] = (mx[0] < NI && mx[1] >= NI) ? 1 : 0;
    }
}

__device__ __forceinline__ int load_idx(const void* p, int i, int is64, int lim)
{
    int v = is64 ? (int)((const long long*)p)[i] : ((const int*)p)[i];
    v = v < 0 ? 0 : v;
    v = v >= lim ? lim - 1 : v;
    return v;
}

// Shared memory layout (floats):
//   [0,16384) W   [16384,16512) b1   [16512,16640) w2   [16640,16644) b2
//   [16644, +8*8*128) xs (8 warps * 8 rows * 128)
constexpr int SM_W  = 0;
constexpr int SM_B1 = 16384;
constexpr int SM_W2 = 16512;
constexpr int SM_B2 = 16640;
constexpr int SM_XS = 16644;
constexpr int SMEM_FLOATS = SM_XS + 8 * 8 * D;   // 24836 floats = 99344 B

// ---------------------------------------------------------------------------
// f32x2 micro-tile: 8 rows x 128 cols. Lane owns column pairs
// (2*lane, 2*lane+1) and (64+2*lane, 64+2*lane+1).
// acc2[e][p] packs the two fp32 accumulators of pair p.
// ---------------------------------------------------------------------------
__device__ __forceinline__ void tile_gemm8(const float* __restrict__ xs,
                                           const float* __restrict__ Ws,
                                           int lane, ull acc2[8][2])
{
    #pragma unroll
    for (int e = 0; e < 8; e++) { acc2[e][0] = 0ull; acc2[e][1] = 0ull; }

    const char* wbase = (const char*)(Ws + 2 * lane);

    #pragma unroll 1
    for (int k = 0; k < D; k += 4) {
        float4 xv[8];
        #pragma unroll
        for (int e = 0; e < 8; e++)
            xv[e] = *(const float4*)(xs + e * D + k);   // broadcast LDS.128

        #pragma unroll
        for (int kk = 0; kk < 4; kk++) {
            ull w0 = *(const ull*)(wbase + (size_t)(k + kk) * D * 4);
            ull w1 = *(const ull*)(wbase + (size_t)(k + kk) * D * 4 + 256);
            #pragma unroll
            for (int e = 0; e < 8; e++) {
                float x = ((const float*)&xv[e])[kk];
                ull x2 = pack2(x, x);
                acc2[e][0] = fma2(x2, w0, acc2[e][0]);
                acc2[e][1] = fma2(x2, w1, acc2[e][1]);
            }
        }
    }
}

// ---------------------------------------------------------------------------
// Node linear: out[r] = X[r] @ W + b
// ---------------------------------------------------------------------------
__global__ void __launch_bounds__(256)
node_linear_kernel(const float* __restrict__ X,
                   const float* __restrict__ W,
                   const float* __restrict__ b,
                   float* __restrict__ out, int N)
{
    extern __shared__ float sm[];
    float* Ws = sm + SM_W;
    float* bs = sm + SM_B1;
    float* xsAll = sm + SM_XS;

    int tid = threadIdx.x;
    {
        const float4* s4 = (const float4*)W;
        float4* d4 = (float4*)Ws;
        for (int i = tid; i < (D * D) / 4; i += blockDim.x) d4[i] = s4[i];
        for (int i = tid; i < D; i += blockDim.x) bs[i] = b[i];
    }
    __syncthreads();

    int wid = tid >> 5, lane = tid & 31;
    float* xs = xsAll + wid * (8 * D);

    float2 bp0 = *(const float2*)(bs + 2 * lane);
    float2 bp1 = *(const float2*)(bs + 64 + 2 * lane);

    int groups = (N + 63) >> 6;
    for (int g = blockIdx.x; g < groups; g += gridDim.x) {
        int rbase = g * 64 + wid * 8;
        __syncwarp();
        #pragma unroll
        for (int e = 0; e < 8; e++) {
            int r = rbase + e;
            if (r < N) {
                float4 v = ((const float4*)(X + (size_t)r * D))[lane];
                ((float4*)(xs + e * D))[lane] = v;
            }
        }
        __syncwarp();

        ull acc2[8][2];
        tile_gemm8(xs, Ws, lane, acc2);

        #pragma unroll
        for (int e = 0; e < 8; e++) {
            int r = rbase + e;
            if (r < N) {
                float a0, a1, a2, a3;
                unpack2(acc2[e][0], a0, a1);
                unpack2(acc2[e][1], a2, a3);
                float2 o0 = make_float2(a0 + bp0.x, a1 + bp0.y);
                float2 o1 = make_float2(a2 + bp1.x, a3 + bp1.y);
                *(float2*)(out + (size_t)r * D + 2 * lane)      = o0;
                *(float2*)(out + (size_t)r * D + 64 + 2 * lane) = o1;
            }
        }
    }
}

// ---------------------------------------------------------------------------
// Edge kernel: gather + add + LReLU -> @W1+b1 -> LReLU -> @W2+b2 -> LReLU
// ---------------------------------------------------------------------------
__global__ void __launch_bounds__(256)
edge_mlp_kernel(const float* __restrict__ uf,
                const float* __restrict__ itf,
                const void* __restrict__ idxA,
                const void* __restrict__ idxB,
                const float* __restrict__ W1,
                const float* __restrict__ b1,
                const float* __restrict__ W2,
                const float* __restrict__ b2,
                float* __restrict__ out,
                int E, int NU, int NI)
{
    extern __shared__ float sm[];
    float* Ws  = sm + SM_W;
    float* b1s = sm + SM_B1;
    float* w2s = sm + SM_W2;
    float* b2s = sm + SM_B2;
    float* xsAll = sm + SM_XS;

    int tid = threadIdx.x;
    {
        const float4* s4 = (const float4*)W1;
        float4* d4 = (float4*)Ws;
        for (int i = tid; i < (D * D) / 4; i += blockDim.x) d4[i] = s4[i];
        for (int i = tid; i < D; i += blockDim.x) { b1s[i] = b1[i]; w2s[i] = W2[i]; }
        if (tid == 0) b2s[0] = b2[0];
    }
    __syncthreads();

    int a64 = g_flags[0], b64 = g_flags[1], swp = g_flags[2];
    const void* src = swp ? idxB : idxA;
    const void* dst = swp ? idxA : idxB;
    int s64 = swp ? b64 : a64;
    int d64 = swp ? a64 : b64;

    int wid = tid >> 5, lane = tid & 31;
    float* xs = xsAll + wid * (8 * D);

    float2 b1p0 = *(const float2*)(b1s + 2 * lane);
    float2 b1p1 = *(const float2*)(b1s + 64 + 2 * lane);
    float2 w2p0 = *(const float2*)(w2s + 2 * lane);
    float2 w2p1 = *(const float2*)(w2s + 64 + 2 * lane);
    float  b2v  = b2s[0];

    int groups = (E + 63) >> 6;
    for (int g = blockIdx.x; g < groups; g += gridDim.x) {
        int ebase = g * 64 + wid * 8;
        __syncwarp();
        #pragma unroll
        for (int e = 0; e < 8; e++) {
            int eid = ebase + e;
            if (eid < E) {
                int s = load_idx(src, eid, s64, NU);
                int d = load_idx(dst, eid, d64, NI);
                float4 a = ((const float4*)(uf  + (size_t)s * D))[lane];
                float4 c = ((const float4*)(itf + (size_t)d * D))[lane];
                float4 v;
                v.x = lrelu(a.x + c.x);
                v.y = lrelu(a.y + c.y);
                v.z = lrelu(a.z + c.z);
                v.w = lrelu(a.w + c.w);
                ((float4*)(xs + e * D))[lane] = v;
            }
        }
        __syncwarp();

        ull acc2[8][2];
        tile_gemm8(xs, Ws, lane, acc2);

        #pragma unroll
        for (int e = 0; e < 8; e++) {
            float a0, a1, a2, a3;
            unpack2(acc2[e][0], a0, a1);
            unpack2(acc2[e][1], a2, a3);
            float p = lrelu(a0 + b1p0.x) * w2p0.x
                    + lrelu(a1 + b1p0.y) * w2p0.y
                    + lrelu(a2 + b1p1.x) * w2p1.x
                    + lrelu(a3 + b1p1.y) * w2p1.y;
            #pragma unroll
            for (int off = 16; off; off >>= 1)
                p += __shfl_xor_sync(0xffffffffu, p, off);
            int eid = ebase + e;
            if (lane == 0 && eid < E)
                out[eid] = lrelu(p + b2v);
        }
    }
}

extern "C" void kernel_launch(void* const* d_in, const int* in_sizes, int n_in,
                              void* d_out, int out_size)
{
    float* out = (float*)d_out;
    int E = out_size;

    // DICT-ORDER binding (verified R16 PASS):
    const float* h_user  = (const float*)d_in[0];
    const float* h_item  = (const float*)d_in[1];
    const void*  idxA    = d_in[2];
    const void*  idxB    = d_in[3];
    const float* W_left  = (const float*)d_in[4];
    const float* b_left  = (const float*)d_in[5];
    const float* W_right = (const float*)d_in[6];
    const float* b_right = (const float*)d_in[7];
    const float* W1      = (const float*)d_in[8];
    const float* b1      = (const float*)d_in[9];
    const float* W2      = (const float*)d_in[10];
    const float* b2      = (const float*)d_in[11];

    long long szU = in_sizes[0], szI = in_sizes[1];
    if (szI > szU) {
        const float* t = h_user; h_user = h_item; h_item = t;
        long long ts = szU; szU = szI; szI = ts;
    }
    int NU = (int)(szU / D); if (NU > MAXU) NU = MAXU;
    int NI = (int)(szI / D); if (NI > MAXI) NI = MAXI;
    int forceA64 = (in_sizes[2] == 2 * E) ? 1 : 0;
    int forceB64 = (in_sizes[3] == 2 * E) ? 1 : 0;

    float *uf, *itf;
    cudaGetSymbolAddress((void**)&uf,  g_uf4);
    cudaGetSymbolAddress((void**)&itf, g_if4);

    size_t smem = SMEM_FLOATS * sizeof(float);
    cudaFuncSetAttribute(node_linear_kernel,
                         cudaFuncAttributeMaxDynamicSharedMemorySize, (int)smem);
    cudaFuncSetAttribute(edge_mlp_kernel,
                         cudaFuncAttributeMaxDynamicSharedMemorySize, (int)smem);

    prepass_kernel<<<1, 1024>>>((const unsigned*)idxA, (const unsigned*)idxB,
                                E, forceA64, forceB64, NI);
    node_linear_kernel<<<(NU + 63) / 64, 256, smem>>>(h_user, W_left, b_left, uf, NU);
    node_linear_kernel<<<(NI + 63) / 64, 256, smem>>>(h_item, W_right, b_right, itf, NI);
    edge_mlp_kernel<<<296, 256, smem>>>(uf, itf, idxA, idxB, W1, b1, W2, b2, out,
                                        E, NU, NI);
}